// round 1
// baseline (speedup 1.0000x reference)
#include <cuda_runtime.h>

typedef unsigned long long u64;
typedef unsigned int u32;

#define NB        8      // batches
#define NCLS      80     // classes
#define KCAND     256    // candidates per class
#define MAXPC     8      // max kept per class
#define NBUCKETS  1024
#define THETA0    1000   // opportunistic capture threshold bucket (score >= 0.9766)
#define CAP       704    // candidate capture capacity per class
#define CLS_PER_CTA 4

static __device__ u64    g_keys[NB * NCLS * MAXPC];
static __device__ float4 g_boxes[NB * NCLS * MAXPC];

__device__ __forceinline__ float clamp01(float x) { return fminf(fmaxf(x, 0.0f), 1.0f); }

// ---------------------------------------------------------------------------
// Kernel 1: per-(batch, 4-class group) exact top-256 select + greedy NMS
// ---------------------------------------------------------------------------
__global__ __launch_bounds__(256) void nms_class_kernel(
    const float* __restrict__ boxes,
    const float* __restrict__ scores,
    int nbox)
{
    const int tid = threadIdx.x;
    const int b   = blockIdx.x / (NCLS / CLS_PER_CTA);
    const int c0  = (blockIdx.x % (NCLS / CLS_PER_CTA)) * CLS_PER_CTA;

    __shared__ u32 sh_hist[CLS_PER_CTA * NBUCKETS];   // 16 KB
    __shared__ u64 sh_cand[CLS_PER_CTA * CAP];        // 22 KB
    __shared__ int sh_cnt[CLS_PER_CTA];
    __shared__ u64 sh_sel[512];                        // 4 KB
    __shared__ u32 sh_part[256];                       // 1 KB
    __shared__ int sh_T, sh_m, sh_kept, sh_curKeep;
    __shared__ float4 sh_curBox;

    for (int i = tid; i < CLS_PER_CTA * NBUCKETS; i += 256) sh_hist[i] = 0;
    if (tid < CLS_PER_CTA) sh_cnt[tid] = 0;
    __syncthreads();

    // ---- Phase 1: single scan of 4 class columns (float4 = 4 classes/box) ----
    const float4* sp = reinterpret_cast<const float4*>(
        scores + (size_t)b * nbox * NCLS + c0);
    for (int i = tid; i < nbox; i += 256) {
        float4 v = sp[(size_t)i * (NCLS / 4)];
        float sv[4] = {v.x, v.y, v.z, v.w};
        #pragma unroll
        for (int k = 0; k < 4; ++k) {
            float s = sv[k];
            int bk = (int)(s * (float)NBUCKETS);
            bk = min(bk, NBUCKETS - 1);
            atomicAdd(&sh_hist[k * NBUCKETS + bk], 1u);
            if (bk >= THETA0) {
                int p = atomicAdd(&sh_cnt[k], 1);
                if (p < CAP)
                    sh_cand[k * CAP + p] =
                        ((u64)__float_as_uint(s) << 32) | (u32)(0xFFFFFFFFu - (u32)i);
            }
        }
    }
    __syncthreads();

    // ---- Per-class: threshold find, gather, sort, NMS ----
    for (int k = 0; k < CLS_PER_CTA; ++k) {
        const int c = c0 + k;

        // Phase 2: suffix scan over histogram -> threshold bucket T
        {
            u32 part = 0;
            #pragma unroll
            for (int j = 0; j < NBUCKETS / 256; ++j)
                part += sh_hist[k * NBUCKETS + tid * (NBUCKETS / 256) + j];
            sh_part[tid] = part;
            __syncthreads();
            for (int off = 1; off < 256; off <<= 1) {
                u32 v = (tid + off < 256) ? sh_part[tid + off] : 0u;
                __syncthreads();
                sh_part[tid] += v;
                __syncthreads();
            }
            if (tid == 0) { sh_T = 0; sh_m = 0; }
            __syncthreads();
            u32 prev = (tid < 255) ? sh_part[tid + 1] : 0u;  // count(bucket >= (tid+1)*4)
            const int base = tid * (NBUCKETS / 256);
            for (int bkt = base + NBUCKETS / 256 - 1; bkt >= base; --bkt) {
                u32 cur = prev + sh_hist[k * NBUCKETS + bkt];
                if (cur >= KCAND && prev < KCAND) sh_T = bkt;  // unique boundary
                prev = cur;
            }
            __syncthreads();
        }
        const int T = sh_T;
        const bool rescan = (T < THETA0) || (sh_cnt[k] > CAP);

        // Phase 3: gather all candidates with bucket >= T
        if (!rescan) {
            int n = sh_cnt[k];
            for (int p = tid; p < n; p += 256) {
                u64 key = sh_cand[k * CAP + p];
                float s = __uint_as_float((u32)(key >> 32));
                int bk = min((int)(s * (float)NBUCKETS), NBUCKETS - 1);
                if (bk >= T) {
                    int q = atomicAdd(&sh_m, 1);
                    if (q < 512) sh_sel[q] = key;
                }
            }
        } else {
            // correctness fallback: full rescan of this class column
            for (int i = tid; i < nbox; i += 256) {
                float s = scores[((size_t)b * nbox + i) * NCLS + c];
                int bk = min((int)(s * (float)NBUCKETS), NBUCKETS - 1);
                if (bk >= T) {
                    int q = atomicAdd(&sh_m, 1);
                    if (q < 512)
                        sh_sel[q] = ((u64)__float_as_uint(s) << 32) |
                                    (u32)(0xFFFFFFFFu - (u32)i);
                }
            }
        }
        __syncthreads();
        int m = min(sh_m, 512);
        for (int p = tid; p < 512; p += 256)
            if (p >= m) sh_sel[p] = 0ull;
        __syncthreads();

        // Phase 4: bitonic sort 512 keys, descending (matches top_k tie-break)
        for (int size = 2; size <= 512; size <<= 1) {
            for (int stride = size >> 1; stride > 0; stride >>= 1) {
                #pragma unroll
                for (int rep = 0; rep < 2; ++rep) {
                    int i = tid + rep * 256;
                    int l = i ^ stride;
                    if (l > i) {
                        u64 a = sh_sel[i], d = sh_sel[l];
                        bool sw = ((i & size) == 0) ? (a < d) : (a > d);
                        if (sw) { sh_sel[i] = d; sh_sel[l] = a; }
                    }
                }
                __syncthreads();
            }
        }

        // Phase 5: load my candidate's box
        u64 mykey = sh_sel[tid];
        float myscore = __uint_as_float((u32)(mykey >> 32));
        bool myvalid = myscore > 0.5f;
        float4 mybox = make_float4(0.f, 0.f, 0.f, 0.f);
        float myarea = 0.f;
        if (myvalid) {
            u32 bi = 0xFFFFFFFFu - (u32)mykey;
            mybox = reinterpret_cast<const float4*>(boxes)[(size_t)b * nbox + bi];
            myarea = fmaxf(mybox.z - mybox.x, 0.f) * fmaxf(mybox.w - mybox.y, 0.f);
        }

        // Phase 6: greedy NMS in score order, early exit at 8 keeps
        if (tid == 0) sh_kept = 0;
        bool suppressed = false;
        __syncthreads();
        for (int i = 0; i < KCAND; ++i) {
            if (tid == i) {
                int kf = (myvalid && !suppressed) ? 1 : 0;
                sh_curKeep = kf;
                if (kf) {
                    sh_curBox = mybox;
                    int slot = sh_kept;
                    sh_kept = slot + 1;
                    int gi = (b * NCLS + c) * MAXPC + slot;
                    g_keys[gi] = ((u64)__float_as_uint(myscore) << 32) |
                                 (u32)(0xFFFFFFFFu - (u32)(c * KCAND + i));
                    g_boxes[gi] = mybox;
                }
            }
            __syncthreads();
            if (sh_curKeep && tid != i) {
                float4 cb = sh_curBox;
                float ca = fmaxf(cb.z - cb.x, 0.f) * fmaxf(cb.w - cb.y, 0.f);
                float iy1 = fmaxf(mybox.x, cb.x);
                float ix1 = fmaxf(mybox.y, cb.y);
                float iy2 = fminf(mybox.z, cb.z);
                float ix2 = fminf(mybox.w, cb.w);
                float inter = fmaxf(iy2 - iy1, 0.f) * fmaxf(ix2 - ix1, 0.f);
                float uni = myarea + ca - inter;
                float iou = (uni > 0.f) ? inter / uni : 0.f;
                if (iou > 0.5f) suppressed = true;
            }
            int kc = sh_kept;
            __syncthreads();
            if (kc >= MAXPC) break;
        }
        // zero-fill unused output slots (graph-replay determinism)
        if (tid >= sh_kept && tid < MAXPC)
            g_keys[(b * NCLS + c) * MAXPC + tid] = 0ull;
        __syncthreads();
    }
}

// ---------------------------------------------------------------------------
// Kernel 2: per-batch top-8 over 640 kept keys, write all 392 outputs
// ---------------------------------------------------------------------------
__global__ __launch_bounds__(256) void final_topk_kernel(float* __restrict__ out)
{
    const int tid = threadIdx.x;
    const int b   = blockIdx.x;
    const int N   = NCLS * MAXPC;  // 640

    __shared__ u64 k_s[NCLS * MAXPC];
    __shared__ u64 red_k[256];
    __shared__ int red_p[256];
    __shared__ u64 selk[8];
    __shared__ int selp[8];
    __shared__ int s_cnt;

    for (int i = tid; i < N; i += 256) k_s[i] = g_keys[b * N + i];
    if (tid == 0) s_cnt = 0;
    __syncthreads();

    for (int r = 0; r < 8; ++r) {
        u64 bk = 0ull; int bp = -1;
        for (int i = tid; i < N; i += 256)
            if (k_s[i] > bk) { bk = k_s[i]; bp = i; }
        red_k[tid] = bk; red_p[tid] = bp;
        __syncthreads();
        for (int off = 128; off > 0; off >>= 1) {
            if (tid < off && red_k[tid + off] > red_k[tid]) {
                red_k[tid] = red_k[tid + off];
                red_p[tid] = red_p[tid + off];
            }
            __syncthreads();
        }
        if (tid == 0) {
            selk[r] = red_k[0];
            selp[r] = red_p[0];
            if (red_p[0] >= 0) k_s[red_p[0]] = 0ull;
        }
        __syncthreads();
    }

    if (tid < 8) {
        u64 key = selk[tid];
        float s = __uint_as_float((u32)(key >> 32));
        bool mask = (s > 0.0f) && (selp[tid] >= 0);
        float4 bx = make_float4(0.f, 0.f, 0.f, 0.f);
        float cls = 0.f;
        if (mask) {
            u32 flat = 0xFFFFFFFFu - (u32)key;
            cls = (float)(flat / KCAND);
            float4 gb = g_boxes[b * NCLS * MAXPC + selp[tid]];
            bx.x = clamp01(gb.x); bx.y = clamp01(gb.y);
            bx.z = clamp01(gb.z); bx.w = clamp01(gb.w);
        }
        int ob = (b * 8 + tid) * 4;
        out[ob + 0] = bx.x; out[ob + 1] = bx.y;
        out[ob + 2] = bx.z; out[ob + 3] = bx.w;
        out[NB * 8 * 4 + b * 8 + tid]          = mask ? s : 0.f;   // scores @256
        out[NB * 8 * 4 + NB * 8 + b * 8 + tid] = mask ? cls : 0.f; // classes @320
        if (mask) atomicAdd(&s_cnt, 1);
    }
    __syncthreads();
    if (tid == 0) out[NB * 8 * 4 + 2 * NB * 8 + b] = (float)s_cnt;  // valid @384
}

// ---------------------------------------------------------------------------
extern "C" void kernel_launch(void* const* d_in, const int* in_sizes, int n_in,
                              void* d_out, int out_size)
{
    const float* boxes  = (const float*)d_in[0];
    const float* scores = (const float*)d_in[1];
    int nbox = in_sizes[0] / (NB * 4);   // boxes: (8, nbox, 1, 4)

    nms_class_kernel<<<NB * (NCLS / CLS_PER_CTA), 256>>>(boxes, scores, nbox);
    final_topk_kernel<<<NB, 256>>>((float*)d_out);
}

// round 2
// speedup vs baseline: 1.5213x; 1.5213x over previous
#include <cuda_runtime.h>

typedef unsigned long long u64;
typedef unsigned int u32;

#define NB        8
#define NCLS      80
#define KCAND     256
#define MAXPC     8
#define CAP       1024          // global per-class candidate capacity
#define LOCCAP    24            // per-CTA per-class staging capacity
#define CHUNK     512           // boxes per pass-A CTA
#define THR       0.9765625f    // capture threshold (bucket 1000/1024)
#define NBUCKETS  1024

static __device__ u64    g_cand[NB * NCLS * CAP];     // ~5.2 MB scratch
static __device__ int    g_cnt[NB * NCLS];
static __device__ u64    g_keys[NB * NCLS * MAXPC];   // (score<<32)|((0x7FFF-flat)<<16)|pos
static __device__ float4 g_boxes[NB * NCLS * MAXPC];

__device__ __forceinline__ float clamp01(float x) { return fminf(fmaxf(x, 0.0f), 1.0f); }

// ---------------------------------------------------------------------------
// Kernel 0: zero the per-class candidate counters
// ---------------------------------------------------------------------------
__global__ void zero_kernel()
{
    int i = blockIdx.x * blockDim.x + threadIdx.x;
    if (i < NB * NCLS) g_cnt[i] = 0;
}

// ---------------------------------------------------------------------------
// Kernel A: coalesced scan of all scores; capture s >= THR into per-class lists
// ---------------------------------------------------------------------------
__global__ __launch_bounds__(256) void scan_kernel(
    const float* __restrict__ scores, int nbox, int nchunks)
{
    const int tid = threadIdx.x;
    const int b   = blockIdx.x / nchunks;
    const int ch  = blockIdx.x % nchunks;
    const int box0 = ch * CHUNK;
    const int boxN = min(CHUNK, nbox - box0);
    if (boxN <= 0) return;

    __shared__ u64 loc[NCLS * LOCCAP];   // 15 KB
    __shared__ int lcnt[NCLS];

    for (int i = tid; i < NCLS; i += 256) lcnt[i] = 0;
    __syncthreads();

    const float4* sp = reinterpret_cast<const float4*>(scores) +
                       (size_t)(b * nbox + box0) * (NCLS / 4);
    const int nf4 = boxN * (NCLS / 4);

    for (int t = tid; t < nf4; t += 256) {
        float4 v = sp[t];
        int box = box0 + t / (NCLS / 4);
        int g   = t % (NCLS / 4);
        float sv[4] = {v.x, v.y, v.z, v.w};
        #pragma unroll
        for (int k = 0; k < 4; ++k) {
            if (sv[k] >= THR) {
                int c = g * 4 + k;
                u64 key = ((u64)__float_as_uint(sv[k]) << 32) |
                          (u32)(0xFFFFFFFFu - (u32)box);
                int p = atomicAdd(&lcnt[c], 1);
                if (p < LOCCAP) {
                    loc[c * LOCCAP + p] = key;
                } else {   // rare local overflow: spill straight to global
                    int q = atomicAdd(&g_cnt[b * NCLS + c], 1);
                    if (q < CAP) g_cand[(size_t)(b * NCLS + c) * CAP + q] = key;
                }
            }
        }
    }
    __syncthreads();

    // flush staging lists (one thread per class; ~12 entries each)
    for (int c = tid; c < NCLS; c += 256) {
        int n = min(lcnt[c], LOCCAP);
        if (n > 0) {
            int base = atomicAdd(&g_cnt[b * NCLS + c], n);
            for (int j = 0; j < n; ++j) {
                int q = base + j;
                if (q < CAP) g_cand[(size_t)(b * NCLS + c) * CAP + q] = loc[c * LOCCAP + j];
            }
        }
    }
}

// ---------------------------------------------------------------------------
// Kernel B: per-(batch,class) exact top-256 (sort captured set) + greedy NMS
// ---------------------------------------------------------------------------
__global__ __launch_bounds__(256) void nms_kernel(
    const float* __restrict__ boxes,
    const float* __restrict__ scores, int nbox)
{
    const int tid = threadIdx.x;
    const int cta = blockIdx.x;
    const int b   = cta / NCLS;
    const int c   = cta % NCLS;

    __shared__ u64 sh_sel[1024];   // 8 KB
    __shared__ u32 sh_hist[NBUCKETS];  // fallback only, 4 KB
    __shared__ u32 sh_part[256];
    __shared__ int sh_T, sh_m, sh_kept, sh_curKeep;
    __shared__ float4 sh_curBox;

    const int cnt = g_cnt[cta];
    int m;

    if (cnt >= KCAND && cnt <= CAP) {
        // common path: captured list is complete and contains the top-256
        for (int i = tid; i < 1024; i += 256)
            sh_sel[i] = (i < cnt) ? g_cand[(size_t)cta * CAP + i] : 0ull;
        m = cnt;
        __syncthreads();
    } else {
        // fallback: full histogram rescan of this class column (never expected)
        for (int i = tid; i < NBUCKETS; i += 256) sh_hist[i] = 0;
        if (tid == 0) { sh_T = 0; sh_m = 0; }
        __syncthreads();
        for (int i = tid; i < nbox; i += 256) {
            float s = scores[((size_t)b * nbox + i) * NCLS + c];
            int bk = min((int)(s * (float)NBUCKETS), NBUCKETS - 1);
            atomicAdd(&sh_hist[bk], 1u);
        }
        __syncthreads();
        // suffix scan -> threshold bucket T
        u32 part = 0;
        #pragma unroll
        for (int j = 0; j < NBUCKETS / 256; ++j)
            part += sh_hist[tid * (NBUCKETS / 256) + j];
        sh_part[tid] = part;
        __syncthreads();
        for (int off = 1; off < 256; off <<= 1) {
            u32 v = (tid + off < 256) ? sh_part[tid + off] : 0u;
            __syncthreads();
            sh_part[tid] += v;
            __syncthreads();
        }
        u32 prev = (tid < 255) ? sh_part[tid + 1] : 0u;
        const int base = tid * (NBUCKETS / 256);
        for (int bkt = base + NBUCKETS / 256 - 1; bkt >= base; --bkt) {
            u32 cur = prev + sh_hist[bkt];
            if (cur >= KCAND && prev < KCAND) sh_T = bkt;
            prev = cur;
        }
        __syncthreads();
        const int T = sh_T;
        for (int i = tid; i < nbox; i += 256) {
            float s = scores[((size_t)b * nbox + i) * NCLS + c];
            int bk = min((int)(s * (float)NBUCKETS), NBUCKETS - 1);
            if (bk >= T) {
                int q = atomicAdd(&sh_m, 1);
                if (q < 1024)
                    sh_sel[q] = ((u64)__float_as_uint(s) << 32) |
                                (u32)(0xFFFFFFFFu - (u32)i);
            }
        }
        __syncthreads();
        m = min(sh_m, 1024);
        for (int i = tid; i < 1024; i += 256)
            if (i >= m) sh_sel[i] = 0ull;
        __syncthreads();
    }

    // bitonic sort (descending); sort 512 if enough, else 1024
    const int size = (m <= 512) ? 512 : 1024;
    for (int sz = 2; sz <= size; sz <<= 1) {
        for (int st = sz >> 1; st > 0; st >>= 1) {
            for (int i = tid; i < size; i += 256) {
                int l = i ^ st;
                if (l > i) {
                    u64 a = sh_sel[i], d = sh_sel[l];
                    bool sw = ((i & sz) == 0) ? (a < d) : (a > d);
                    if (sw) { sh_sel[i] = d; sh_sel[l] = a; }
                }
            }
            __syncthreads();
        }
    }

    // load my candidate's box
    u64 mykey = sh_sel[tid];
    float myscore = __uint_as_float((u32)(mykey >> 32));
    bool myvalid = myscore > 0.5f;
    float4 mybox = make_float4(0.f, 0.f, 0.f, 0.f);
    float myarea = 0.f;
    if (myvalid) {
        u32 bi = 0xFFFFFFFFu - (u32)mykey;
        mybox = reinterpret_cast<const float4*>(boxes)[(size_t)b * nbox + bi];
        myarea = fmaxf(mybox.z - mybox.x, 0.f) * fmaxf(mybox.w - mybox.y, 0.f);
    }

    // greedy NMS in score order, early exit at 8 keeps
    if (tid == 0) sh_kept = 0;
    bool suppressed = false;
    __syncthreads();
    for (int i = 0; i < KCAND; ++i) {
        if (tid == i) {
            int kf = (myvalid && !suppressed) ? 1 : 0;
            sh_curKeep = kf;
            if (kf) {
                sh_curBox = mybox;
                int slot = sh_kept;
                sh_kept = slot + 1;
                int flat = c * KCAND + i;           // index within the 80*256 flat array
                int pos  = c * MAXPC + slot;        // position within this batch's kept array
                g_keys[b * NCLS * MAXPC + pos] =
                    ((u64)__float_as_uint(myscore) << 32) |
                    ((u64)(u32)(0x7FFF - flat) << 16) | (u32)pos;
                g_boxes[b * NCLS * MAXPC + pos] = mybox;
            }
        }
        __syncthreads();
        if (sh_curKeep && tid != i) {
            float4 cb = sh_curBox;
            float ca = fmaxf(cb.z - cb.x, 0.f) * fmaxf(cb.w - cb.y, 0.f);
            float iy1 = fmaxf(mybox.x, cb.x);
            float ix1 = fmaxf(mybox.y, cb.y);
            float iy2 = fminf(mybox.z, cb.z);
            float ix2 = fminf(mybox.w, cb.w);
            float inter = fmaxf(iy2 - iy1, 0.f) * fmaxf(ix2 - ix1, 0.f);
            float uni = myarea + ca - inter;
            float iou = (uni > 0.f) ? inter / uni : 0.f;
            if (iou > 0.5f) suppressed = true;
        }
        int kc = sh_kept;
        __syncthreads();
        if (kc >= MAXPC) break;
    }
    if (tid >= sh_kept && tid < MAXPC)
        g_keys[(b * NCLS + c) * MAXPC + tid] = 0ull;
}

// ---------------------------------------------------------------------------
// Kernel C: per-batch top-8 over 640 kept keys (register + shuffle reduction)
// ---------------------------------------------------------------------------
__global__ __launch_bounds__(256) void final_kernel(float* __restrict__ out)
{
    const int tid  = threadIdx.x;
    const int lane = tid & 31;
    const int wid  = tid >> 5;
    const int b    = blockIdx.x;
    const u64* gk  = g_keys + (size_t)b * NCLS * MAXPC;

    u64 k0 = gk[tid];
    u64 k1 = gk[tid + 256];
    u64 k2 = (tid < 128) ? gk[tid + 512] : 0ull;

    __shared__ u64 wmax[8];
    __shared__ u64 sel[8];

    for (int r = 0; r < 8; ++r) {
        u64 mx = k0;
        if (k1 > mx) mx = k1;
        if (k2 > mx) mx = k2;
        #pragma unroll
        for (int off = 16; off > 0; off >>= 1) {
            u64 o = __shfl_xor_sync(0xFFFFFFFFu, mx, off);
            if (o > mx) mx = o;
        }
        if (lane == 0) wmax[wid] = mx;
        __syncthreads();
        if (wid == 0) {
            u64 v = (lane < 8) ? wmax[lane] : 0ull;
            #pragma unroll
            for (int off = 4; off > 0; off >>= 1) {
                u64 o = __shfl_xor_sync(0xFFFFFFFFu, v, off);
                if (o > v) v = o;
            }
            if (lane == 0) sel[r] = v;
        }
        __syncthreads();
        u64 best = sel[r];
        if (k0 == best) k0 = 0ull;
        if (k1 == best) k1 = 0ull;
        if (k2 == best) k2 = 0ull;
    }

    if (tid < 8) {
        u64 key = sel[tid];
        float s = __uint_as_float((u32)(key >> 32));
        bool mask = s > 0.0f;
        float4 bx = make_float4(0.f, 0.f, 0.f, 0.f);
        float cls = 0.f;
        if (mask) {
            int pos  = (int)(key & 0xFFFFu);
            int flat = 0x7FFF - (int)((key >> 16) & 0x7FFFu);
            cls = (float)(flat / KCAND);
            float4 gb = g_boxes[(size_t)b * NCLS * MAXPC + pos];
            bx.x = clamp01(gb.x); bx.y = clamp01(gb.y);
            bx.z = clamp01(gb.z); bx.w = clamp01(gb.w);
        }
        int ob = (b * 8 + tid) * 4;
        out[ob + 0] = bx.x; out[ob + 1] = bx.y;
        out[ob + 2] = bx.z; out[ob + 3] = bx.w;
        out[NB * 8 * 4 + b * 8 + tid]          = mask ? s : 0.f;   // scores @256
        out[NB * 8 * 4 + NB * 8 + b * 8 + tid] = mask ? cls : 0.f; // classes @320
        unsigned bal = __ballot_sync(0xFFu, mask) & 0xFFu;
        if (tid == 0)
            out[NB * 8 * 4 + 2 * NB * 8 + b] = (float)__popc(bal);  // valid @384
    }
}

// ---------------------------------------------------------------------------
extern "C" void kernel_launch(void* const* d_in, const int* in_sizes, int n_in,
                              void* d_out, int out_size)
{
    const float* boxes  = (const float*)d_in[0];
    const float* scores = (const float*)d_in[1];
    int nbox = in_sizes[0] / (NB * 4);
    int nchunks = (nbox + CHUNK - 1) / CHUNK;

    zero_kernel<<<(NB * NCLS + 255) / 256, 256>>>();
    scan_kernel<<<NB * nchunks, 256>>>(scores, nbox, nchunks);
    nms_kernel<<<NB * NCLS, 256>>>(boxes, scores, nbox);
    final_kernel<<<NB, 256>>>((float*)d_out);
}

// round 3
// speedup vs baseline: 1.9692x; 1.2944x over previous
#include <cuda_runtime.h>

typedef unsigned long long u64;
typedef unsigned int u32;

#define NB         8
#define NCLS       80
#define KCAND      256
#define MAXPC      8
#define LOCCAP     32                       // per-(class,chunk) segment capacity
#define CHUNK      512                      // boxes per scan CTA
#define NCHUNK_MAX 64
#define CAPC       (NCHUNK_MAX * LOCCAP)    // 2048 slots per (batch,class)
#define MAXK       768                      // max candidates held for NMS
#define THR        0.9765625f               // capture threshold
#define NBUCKETS   1024

static __device__ u64    g_cand[NB * NCLS * CAPC];          // ~10.5 MB scratch
static __device__ int    g_ccnt[NB * NCLS * NCHUNK_MAX];    // raw per-segment counts
static __device__ u64    g_keys[NB * NCLS * MAXPC];         // (score<<32)|((0x7FFF-flat)<<16)|pos
static __device__ float4 g_boxes[NB * NCLS * MAXPC];
static __device__ unsigned int g_done;                      // zero-init; reset by finisher

__device__ __forceinline__ float clamp01(float x) { return fminf(fmaxf(x, 0.0f), 1.0f); }

// ---------------------------------------------------------------------------
// Kernel A: coalesced scan; capture s >= THR into per-(class,chunk) segments.
// No global atomics, nothing to pre-zero: counts are overwritten every launch.
// ---------------------------------------------------------------------------
__global__ __launch_bounds__(256) void scan_kernel(
    const float* __restrict__ scores, int nbox, int nchunks)
{
    const int tid = threadIdx.x;
    const int b   = blockIdx.x / nchunks;
    const int ch  = blockIdx.x % nchunks;
    const int box0 = ch * CHUNK;
    const int boxN = min(CHUNK, nbox - box0);

    __shared__ u64 loc[NCLS * LOCCAP];   // 20 KB
    __shared__ int lcnt[NCLS];

    for (int i = tid; i < NCLS; i += 256) lcnt[i] = 0;
    __syncthreads();

    if (boxN > 0) {
        const float4* sp = reinterpret_cast<const float4*>(scores) +
                           (size_t)(b * nbox + box0) * (NCLS / 4);
        const int nf4 = boxN * (NCLS / 4);
        for (int t = tid; t < nf4; t += 256) {
            float4 v = sp[t];
            int box = box0 + t / (NCLS / 4);
            int g   = t % (NCLS / 4);
            float sv[4] = {v.x, v.y, v.z, v.w};
            #pragma unroll
            for (int k = 0; k < 4; ++k) {
                if (sv[k] >= THR) {
                    int c = g * 4 + k;
                    int p = atomicAdd(&lcnt[c], 1);
                    if (p < LOCCAP)
                        loc[c * LOCCAP + p] =
                            ((u64)__float_as_uint(sv[k]) << 32) |
                            (u32)(0xFFFFFFFFu - (u32)box);
                }
            }
        }
    }
    __syncthreads();

    if (ch < NCHUNK_MAX) {
        for (int idx = tid; idx < NCLS * LOCCAP; idx += 256) {
            int cc = idx / LOCCAP, j = idx % LOCCAP;
            if (j < min(lcnt[cc], LOCCAP))
                g_cand[(size_t)(b * NCLS + cc) * CAPC + ch * LOCCAP + j] = loc[idx];
        }
        for (int cc = tid; cc < NCLS; cc += 256)
            g_ccnt[(b * NCLS + cc) * NCHUNK_MAX + ch] = lcnt[cc];  // raw (may exceed LOCCAP)
    }
}

// ---------------------------------------------------------------------------
// Kernel B: per-(batch,class) greedy NMS via iterative block-argmax (no sort),
// plus fused per-batch top-8 epilogue run by the last CTA to finish.
// ---------------------------------------------------------------------------
__global__ __launch_bounds__(256) void nms_kernel(
    const float4* __restrict__ boxes4,
    const float*  __restrict__ scores,
    float* __restrict__ out,
    int nbox, int nchunks)
{
    const int tid  = threadIdx.x;
    const int lane = tid & 31;
    const int wid  = tid >> 5;
    const int cta  = blockIdx.x;
    const int b    = cta / NCLS;
    const int c    = cta % NCLS;

    __shared__ float4 sh_box[MAXK];              // 12 KB
    __shared__ u64    sh_keys[MAXK];             // 6 KB (aliased as hist in fallback)
    __shared__ int    sh_segoff[NCHUNK_MAX + 1];
    __shared__ int    sh_total, sh_ovf, sh_T, sh_m, sh_keptCnt;
    __shared__ u64    sh_red[8];
    __shared__ u64    sh_best;
    __shared__ float4 sh_kbox[MAXPC];
    __shared__ float  sh_karea[MAXPC];
    __shared__ int    sh_last;

    const int nck = min(nchunks, NCHUNK_MAX);

    if (tid < NCHUNK_MAX)
        sh_segoff[tid] = (tid < nck) ? g_ccnt[cta * NCHUNK_MAX + tid] : 0;
    __syncthreads();
    if (tid == 0) {
        int acc = 0, ovf = (nchunks > NCHUNK_MAX);
        for (int ch = 0; ch < nck; ++ch) {
            int cnt = sh_segoff[ch];
            if (cnt > LOCCAP) { ovf = 1; cnt = LOCCAP; }
            sh_segoff[ch] = acc;
            acc += cnt;
        }
        sh_segoff[nck] = acc;
        sh_total = acc;
        sh_ovf = ovf;
        sh_m = 0;
        sh_T = 0;
        sh_keptCnt = 0;
    }
    __syncthreads();

    int m;
    const bool fb = sh_ovf || (sh_total < KCAND) || (sh_total > MAXK);

    if (!fb) {
        // common path: gather segments into dense smem key list
        m = sh_total;
        for (int ch = wid; ch < nck; ch += 8) {
            int off = sh_segoff[ch];
            int n   = sh_segoff[ch + 1] - off;
            if (lane < n)
                sh_keys[off + lane] = g_cand[(size_t)cta * CAPC + ch * LOCCAP + lane];
        }
        __syncthreads();
    } else {
        // exact fallback: histogram over the full class column (never expected)
        u32* hist = (u32*)sh_keys;           // 4 KB
        u32* part = hist + NBUCKETS;         // 1 KB
        for (int i = tid; i < NBUCKETS; i += 256) hist[i] = 0;
        __syncthreads();
        for (int i = tid; i < nbox; i += 256) {
            float s = scores[((size_t)b * nbox + i) * NCLS + c];
            atomicAdd(&hist[min((int)(s * (float)NBUCKETS), NBUCKETS - 1)], 1u);
        }
        __syncthreads();
        u32 p = 0;
        #pragma unroll
        for (int j = 0; j < NBUCKETS / 256; ++j)
            p += hist[tid * (NBUCKETS / 256) + j];
        part[tid] = p;
        __syncthreads();
        for (int off = 1; off < 256; off <<= 1) {
            u32 v = (tid + off < 256) ? part[tid + off] : 0u;
            __syncthreads();
            part[tid] += v;
            __syncthreads();
        }
        u32 prev = (tid < 255) ? part[tid + 1] : 0u;
        const int base = tid * (NBUCKETS / 256);
        for (int bkt = base + NBUCKETS / 256 - 1; bkt >= base; --bkt) {
            u32 cur = prev + hist[bkt];
            if (cur >= KCAND && prev < KCAND) sh_T = bkt;
            prev = cur;
        }
        __syncthreads();
        const int T = sh_T;
        __syncthreads();   // hist no longer needed; sh_keys region reused below
        for (int i = tid; i < nbox; i += 256) {
            float s = scores[((size_t)b * nbox + i) * NCLS + c];
            int bk = min((int)(s * (float)NBUCKETS), NBUCKETS - 1);
            if (bk >= T) {
                int q = atomicAdd(&sh_m, 1);
                if (q < MAXK)
                    sh_keys[q] = ((u64)__float_as_uint(s) << 32) |
                                 (u32)(0xFFFFFFFFu - (u32)i);
            }
        }
        __syncthreads();
        m = min(sh_m, MAXK);
    }

    for (int i = tid; i < MAXK; i += 256)
        if (i >= m) sh_keys[i] = 0ull;
    __syncthreads();

    // keys -> registers; prefetch boxes -> smem (parallel, high MLP)
    u64 kr[3];
    #pragma unroll
    for (int r = 0; r < 3; ++r) {
        int slot = tid + r * 256;
        u64 k = sh_keys[slot];
        kr[r] = k;
        if (k) {
            u32 bi = 0xFFFFFFFFu - (u32)k;
            sh_box[slot] = boxes4[(size_t)b * nbox + bi];
        }
    }
    __syncthreads();

    // iterative argmax greedy NMS: ~9 pops expected, exact order
    int pops = 0;
    while (true) {
        u64 mx = kr[0];
        if (kr[1] > mx) mx = kr[1];
        if (kr[2] > mx) mx = kr[2];
        #pragma unroll
        for (int off = 16; off; off >>= 1) {
            u64 o = __shfl_xor_sync(0xFFFFFFFFu, mx, off);
            if (o > mx) mx = o;
        }
        if (lane == 0) sh_red[wid] = mx;
        __syncthreads();
        if (wid == 0) {
            u64 v = (lane < 8) ? sh_red[lane] : 0ull;
            #pragma unroll
            for (int off = 4; off; off >>= 1) {
                u64 o = __shfl_xor_sync(0xFFFFFFFFu, v, off);
                if (o > v) v = o;
            }
            if (lane == 0) sh_best = v;
        }
        __syncthreads();
        const u64 best = sh_best;
        if ((u32)(best >> 32) <= 0x3F000000u) break;   // score <= 0.5f (or empty)

        #pragma unroll
        for (int r = 0; r < 3; ++r) {
            if (kr[r] == best) {   // unique owner (idx encoded in key)
                kr[r] = 0ull;
                int slot = tid + r * 256;
                float4 bx = sh_box[slot];
                float area = fmaxf(bx.z - bx.x, 0.f) * fmaxf(bx.w - bx.y, 0.f);
                int kc = sh_keptCnt;
                bool sup = false;
                for (int j = 0; j < kc; ++j) {
                    float4 kb = sh_kbox[j];
                    float iy1 = fmaxf(bx.x, kb.x), ix1 = fmaxf(bx.y, kb.y);
                    float iy2 = fminf(bx.z, kb.z), ix2 = fminf(bx.w, kb.w);
                    float inter = fmaxf(iy2 - iy1, 0.f) * fmaxf(ix2 - ix1, 0.f);
                    float uni = area + sh_karea[j] - inter;
                    float iou = (uni > 0.f) ? inter / uni : 0.f;
                    if (iou > 0.5f) sup = true;
                }
                if (!sup) {
                    sh_kbox[kc] = bx;
                    sh_karea[kc] = area;
                    sh_keptCnt = kc + 1;
                    int flat = c * KCAND + pops;
                    int pos  = c * MAXPC + kc;
                    g_keys[b * NCLS * MAXPC + pos] =
                        ((u64)(u32)(best >> 32) << 32) |
                        ((u64)(u32)(0x7FFF - flat) << 16) | (u32)pos;
                    g_boxes[b * NCLS * MAXPC + pos] = bx;
                }
            }
        }
        __syncthreads();
        ++pops;
        if (sh_keptCnt >= MAXPC || pops >= KCAND) break;
    }

    // zero unused kept slots (graph-replay determinism)
    if (tid >= sh_keptCnt && tid < MAXPC)
        g_keys[b * NCLS * MAXPC + c * MAXPC + tid] = 0ull;
    __syncthreads();

    // ---- fused finisher: last CTA does the per-batch top-8 ----
    if (tid == 0) {
        __threadfence();
        sh_last = (atomicAdd(&g_done, 1u) == (unsigned)(NB * NCLS - 1));
    }
    __syncthreads();
    if (!sh_last) return;
    if (tid == 0) g_done = 0u;     // reset for next graph replay
    __threadfence();

    // one warp per batch: 640 keys = 20 per lane, zero barriers
    const int b2 = wid;            // 8 warps == 8 batches
    u64 kv[20];
    #pragma unroll
    for (int j = 0; j < 20; ++j)
        kv[j] = g_keys[b2 * (NCLS * MAXPC) + j * 32 + lane];

    u64 sel[8];
    #pragma unroll
    for (int r = 0; r < 8; ++r) {
        u64 mx = 0ull;
        #pragma unroll
        for (int j = 0; j < 20; ++j) if (kv[j] > mx) mx = kv[j];
        #pragma unroll
        for (int off = 16; off; off >>= 1) {
            u64 o = __shfl_xor_sync(0xFFFFFFFFu, mx, off);
            if (o > mx) mx = o;
        }
        sel[r] = mx;
        #pragma unroll
        for (int j = 0; j < 20; ++j) if (kv[j] == mx) kv[j] = 0ull;
    }

    u64 mykey = (lane < 8) ? sel[lane] : 0ull;
    float s = __uint_as_float((u32)(mykey >> 32));
    bool mask = s > 0.0f;
    if (lane < 8) {
        float4 bx = make_float4(0.f, 0.f, 0.f, 0.f);
        float cls = 0.f;
        if (mask) {
            int pos  = (int)(mykey & 0xFFFFu);
            int flat = 0x7FFF - (int)((mykey >> 16) & 0x7FFFu);
            cls = (float)(flat / KCAND);
            float4 gb = g_boxes[b2 * (NCLS * MAXPC) + pos];
            bx.x = clamp01(gb.x); bx.y = clamp01(gb.y);
            bx.z = clamp01(gb.z); bx.w = clamp01(gb.w);
        }
        int ob = (b2 * 8 + lane) * 4;
        out[ob + 0] = bx.x; out[ob + 1] = bx.y;
        out[ob + 2] = bx.z; out[ob + 3] = bx.w;
        out[NB * 8 * 4 + b2 * 8 + lane]          = mask ? s : 0.f;   // scores  @256
        out[NB * 8 * 4 + NB * 8 + b2 * 8 + lane] = mask ? cls : 0.f; // classes @320
    }
    unsigned bal = __ballot_sync(0xFFFFFFFFu, (lane < 8) && mask);
    if (lane == 0)
        out[NB * 8 * 4 + 2 * NB * 8 + b2] = (float)__popc(bal);      // valid @384
}

// ---------------------------------------------------------------------------
extern "C" void kernel_launch(void* const* d_in, const int* in_sizes, int n_in,
                              void* d_out, int out_size)
{
    const float* boxes  = (const float*)d_in[0];
    const float* scores = (const float*)d_in[1];
    int nbox = in_sizes[0] / (NB * 4);
    int nchunks = (nbox + CHUNK - 1) / CHUNK;

    scan_kernel<<<NB * nchunks, 256>>>(scores, nbox, nchunks);
    nms_kernel<<<NB * NCLS, 256>>>((const float4*)boxes, scores, (float*)d_out,
                                   nbox, nchunks);
}